// round 5
// baseline (speedup 1.0000x reference)
#include <cuda_runtime.h>
#include <cstdint>

#define BATCH 128
#define NPRI  8732
#define NOBJ  16
#define NCLS  21
#define THRESH 0.5f
#define NSLICE 8
#define SLICE  1092     // ceil(8732 / 8); last slice bounds-checked
#define CEB    35       // ce blocks per image (35*256 >= 8732)

// ---------------- scratch (static device globals; zero-initialized) ----------
__device__ float              g_btov[BATCH * NPRI];
__device__ uint8_t            g_bti [BATCH * NPRI];
__device__ uint8_t            g_ct  [BATCH * NPRI];
__device__ uint8_t            g_of  [BATCH * NPRI];
__device__ float              g_ce  [BATCH * NPRI];
__device__ unsigned long long g_best[BATCH * NOBJ];  // re-zeroed by k3 each launch
__device__ int                g_npos[BATCH];         // re-zeroed by k3 each launch
__device__ float              g_nposf[BATCH];
__device__ float              g_locs[BATCH];
__device__ float              g_pces[BATCH];
__device__ float              g_negs[BATCH];
__device__ unsigned int       g_ticket;              // reset by last block each launch

// ---------------- helpers -----------------------------------------------------
__device__ __forceinline__ float sl1(float x) {
    float a = fabsf(x);
    return (a < 1.f) ? 0.5f * a * a : a - 0.5f;
}

__device__ __forceinline__ float brSumF(float v, float* s) {
    int lane = threadIdx.x & 31, wid = threadIdx.x >> 5;
    int nw = (blockDim.x + 31) >> 5;
    #pragma unroll
    for (int o = 16; o; o >>= 1) v += __shfl_xor_sync(0xFFFFFFFFu, v, o);
    if (lane == 0) s[wid] = v;
    __syncthreads();
    if (wid == 0) {
        float r = (lane < nw) ? s[lane] : 0.f;
        #pragma unroll
        for (int o = 16; o; o >>= 1) r += __shfl_xor_sync(0xFFFFFFFFu, r, o);
        if (lane == 0) s[0] = r;
    }
    __syncthreads();
    float r = s[0];
    __syncthreads();
    return r;
}

__device__ __forceinline__ int brSumI(int v, int* s) {
    int lane = threadIdx.x & 31, wid = threadIdx.x >> 5;
    int nw = (blockDim.x + 31) >> 5;
    #pragma unroll
    for (int o = 16; o; o >>= 1) v += __shfl_xor_sync(0xFFFFFFFFu, v, o);
    if (lane == 0) s[wid] = v;
    __syncthreads();
    if (wid == 0) {
        int r = (lane < nw) ? s[lane] : 0;
        #pragma unroll
        for (int o = 16; o; o >>= 1) r += __shfl_xor_sync(0xFFFFFFFFu, r, o);
        if (lane == 0) s[0] = r;
    }
    __syncthreads();
    int r = s[0];
    __syncthreads();
    return r;
}

// ---------------- K1: IoU + argmaxes (fast-approx ordering, exact threshold) --
// 1024 blocks = 8 slices per image, 256 threads, <=85 regs (3 blocks/SM).
__global__ __launch_bounds__(256, 3)
void k1_iou(const float* __restrict__ boxes, const float* __restrict__ priors) {
    const int b   = blockIdx.x >> 3;
    const int s   = blockIdx.x & 7;
    const int tid = threadIdx.x;
    const int lo  = s * SLICE;
    const int hi  = min(lo + SLICE, NPRI);

    __shared__ float4 s_t[NOBJ];     // truth boxes (x1,y1,x2,y2)
    __shared__ float  s_ta[NOBJ];    // truth areas
    __shared__ unsigned long long s_red[NOBJ][8];

    if (tid < NOBJ) {
        float4 t = ((const float4*)boxes)[b * NOBJ + tid];
        s_t[tid]  = t;
        s_ta[tid] = (t.z - t.x) * (t.w - t.y);
    }
    __syncthreads();

    // per-truth best approx IoU + prior index
    float    bv[NOBJ];
    unsigned bp[NOBJ];
    #pragma unroll
    for (int o = 0; o < NOBJ; o++) { bv[o] = -1.f; bp[o] = 0u; }

    for (int p = lo + tid; p < hi; p += 256) {
        float4 pr = ((const float4*)priors)[p];
        float hw = 0.5f * pr.z, hh = 0.5f * pr.w;
        float px1 = pr.x - hw, py1 = pr.y - hh, px2 = pr.x + hw, py2 = pr.y + hh;
        float ap = pr.z * pr.w;
        float pv = -1.f; int po = 0;
        #pragma unroll
        for (int o = 0; o < NOBJ; o++) {
            float4 t = s_t[o];
            float ix = fmaxf(fminf(t.z, px2) - fmaxf(t.x, px1), 0.f);
            float iy = fmaxf(fminf(t.w, py2) - fmaxf(t.y, py1), 0.f);
            float inter = ix * iy;
            float den   = (s_ta[o] + ap) - inter;
            float v     = __fdividef(inter, den);   // MUFU.RCP+FMUL: ordering only
            bool g1 = v > pv;                       // first truth on tie
            pv = g1 ? v : pv;  po = g1 ? o : po;
            bool g2 = v > bv[o];                    // first prior on tie
            bv[o] = g2 ? v : bv[o];
            bp[o] = g2 ? (unsigned)p : bp[o];
        }
        // exact IoU for the winning truth only (threshold semantics exact)
        {
            float4 t = s_t[po];
            float ix = fmaxf(fminf(t.z, px2) - fmaxf(t.x, px1), 0.f);
            float iy = fmaxf(fminf(t.w, py2) - fmaxf(t.y, py1), 0.f);
            float inter = ix * iy;
            float den   = (s_ta[po] + ap) - inter;
            g_btov[b * NPRI + p] = inter / den;     // div.rn, once per prior
            g_bti [b * NPRI + p] = (uint8_t)po;
        }
    }

    int lane = tid & 31, wid = tid >> 5;
    #pragma unroll
    for (int o = 0; o < NOBJ; o++) {
        unsigned long long key =
            ((unsigned long long)__float_as_uint(bv[o]) << 32) |
            (unsigned)(0xFFFFFFFFu - bp[o]);        // tie -> smaller p wins
        #pragma unroll
        for (int off = 16; off; off >>= 1) {
            unsigned long long u = __shfl_xor_sync(0xFFFFFFFFu, key, off);
            key = (u > key) ? u : key;
        }
        if (lane == 0) s_red[o][wid] = key;
    }
    __syncthreads();
    if (tid < NOBJ) {
        unsigned long long m = 0ULL;
        #pragma unroll
        for (int w = 0; w < 8; w++) {
            unsigned long long u = s_red[tid][w];
            m = (u > m) ? u : m;
        }
        atomicMax(&g_best[b * NOBJ + tid], m);      // order-independent merge
    }
}

// ---------------- K2: force-assign + conf target + cross entropy --------------
__global__ __launch_bounds__(256)
void k2_ce(const float* __restrict__ conf, const int* __restrict__ labels) {
    const int blk = blockIdx.x;
    const int b   = blk / CEB;
    const int t   = blk % CEB;
    const int tid = threadIdx.x;
    const int r0  = t * 256;
    const int nr  = min(256, NPRI - r0);

    __shared__ float    s_rows[256 * NCLS];
    __shared__ int      s_lab[NOBJ];
    __shared__ unsigned s_fp[NOBJ];
    __shared__ int      s_wc[8];

    if (tid < NOBJ) {
        s_lab[tid] = labels[b * NOBJ + tid];
        s_fp[tid]  = 0xFFFFFFFFu - (unsigned)(g_best[b * NOBJ + tid] & 0xFFFFFFFFULL);
    }
    const int nf4 = nr * NCLS / 4;
    const float4* src = (const float4*)(conf + ((size_t)b * NPRI + r0) * NCLS);
    #pragma unroll
    for (int i = 0; i < 6; i++) {
        int j = tid + i * 256;
        if (j < nf4) ((float4*)s_rows)[j] = src[j];
    }
    __syncthreads();

    int isp = 0;
    if (tid < nr) {
        int p = r0 + tid;
        size_t idx = (size_t)b * NPRI + p;
        float ov = g_btov[idx];
        int   o  = g_bti[idx];
        #pragma unroll
        for (int oo = 0; oo < NOBJ; oo++) {          // ascending: last truth wins
            bool f = (s_fp[oo] == (unsigned)p);
            ov = f ? 2.0f : ov;
            o  = f ? oo : o;
        }
        int ct = (ov < THRESH) ? 0 : (s_lab[o] + 1);
        g_ct[idx] = (uint8_t)ct;
        g_of[idx] = (uint8_t)o;
        isp = (ct > 0);
        const float* v = s_rows + tid * NCLS;        // stride 21: conflict-free
        float m = v[0];
        #pragma unroll
        for (int c = 1; c < NCLS; c++) m = fmaxf(m, v[c]);
        float ssum = 0.f;
        #pragma unroll
        for (int c = 0; c < NCLS; c++) ssum += __expf(v[c] - m);
        g_ce[idx] = m + __logf(ssum) - v[ct];
    }
    unsigned bal = __ballot_sync(0xFFFFFFFFu, isp);
    if ((tid & 31) == 0) s_wc[tid >> 5] = __popc(bal);
    __syncthreads();
    if (tid == 0) {
        int c = 0;
        #pragma unroll
        for (int w = 0; w < 8; w++) c += s_wc[w];
        atomicAdd(&g_npos[b], c);
    }
}

// ---------------- K3: loc loss + register-resident top-K + fused final --------
__global__ __launch_bounds__(1024)
void k3_select(const float* __restrict__ loc_preds,
               const float* __restrict__ boxes,
               const float* __restrict__ priors,
               float* __restrict__ out) {
    const int b   = blockIdx.x;
    const int tid = threadIdx.x;

    __shared__ float s_tx1[NOBJ], s_ty1[NOBJ], s_tx2[NOBJ], s_ty2[NOBJ];
    __shared__ float s_redf[32];
    __shared__ int   s_redi[32];
    __shared__ int   s_wc[32];
    __shared__ int   s_bc[4];

    if (tid < NOBJ) {
        s_tx1[tid] = boxes[(b * NOBJ + tid) * 4 + 0];
        s_ty1[tid] = boxes[(b * NOBJ + tid) * 4 + 1];
        s_tx2[tid] = boxes[(b * NOBJ + tid) * 4 + 2];
        s_ty2[tid] = boxes[(b * NOBJ + tid) * 4 + 3];
    }
    if (tid == 0) s_bc[0] = g_npos[b];
    __syncthreads();
    const int npos = s_bc[0];

    unsigned u[9];
    float posce = 0.f, locsum = 0.f;
    #pragma unroll
    for (int i = 0; i < 9; i++) {
        int p = tid + i * 1024;
        u[i] = 0u;
        if (p < NPRI) {
            size_t idx = (size_t)b * NPRI + p;
            float ce = g_ce[idx];
            if (g_ct[idx] > 0) {
                posce += ce;
                int o = g_of[idx];
                float4 pr = ((const float4*)priors)[p];
                float tx1 = s_tx1[o], ty1 = s_ty1[o], tx2 = s_tx2[o], ty2 = s_ty2[o];
                float g0 = ((tx1 + tx2) * 0.5f - pr.x) / (0.1f * pr.z);
                float g1 = ((ty1 + ty2) * 0.5f - pr.y) / (0.1f * pr.w);
                float g2 = __logf((tx2 - tx1) / pr.z) * 5.0f;
                float g3 = __logf((ty2 - ty1) / pr.w) * 5.0f;
                float4 lp = ((const float4*)loc_preds)[(size_t)b * NPRI + p];
                locsum += sl1(lp.x - g0) + sl1(lp.y - g1)
                        + sl1(lp.z - g2) + sl1(lp.w - g3);
            } else {
                u[i] = __float_as_uint(ce);   // negatives only; ce >= 0
            }
        }
    }

    float pcT = brSumF(posce, s_redf);
    float lcT = brSumF(locsum, s_redf);

    int K = 3 * npos; if (K > NPRI) K = NPRI;
    float negsum = 0.f;
    if (K > 0) {
        unsigned prefix = 0u;
        for (int bit = 30; bit >= 0; bit--) {
            unsigned cand = prefix | (1u << bit);
            int c = 0;
            #pragma unroll
            for (int i = 0; i < 9; i++)
                c += __popc(__ballot_sync(0xFFFFFFFFu, u[i] >= cand));
            if ((tid & 31) == 0) s_wc[tid >> 5] = c;
            __syncthreads();
            if (tid < 32) {
                int t2 = s_wc[tid];
                #pragma unroll
                for (int off = 16; off; off >>= 1)
                    t2 += __shfl_xor_sync(0xFFFFFFFFu, t2, off);
                if (tid == 0) s_bc[1] = t2;
            }
            __syncthreads();
            if (s_bc[1] >= K) prefix = cand;
        }
        float vK = __uint_as_float(prefix);
        float sgt = 0.f; int cgt = 0;
        #pragma unroll
        for (int i = 0; i < 9; i++) {
            float v = __uint_as_float(u[i]);
            if (v > vK) { sgt += v; cgt++; }
        }
        sgt = brSumF(sgt, s_redf);
        cgt = brSumI(cgt, s_redi);
        negsum = sgt + (float)(K - cgt) * vK;
    }

    if (tid == 0) {
        g_locs[b]  = lcT;
        g_pces[b]  = pcT;
        g_negs[b]  = negsum;
        g_nposf[b] = (float)npos;
    }
    if (tid < NOBJ) g_best[b * NOBJ + tid] = 0ULL;   // re-zero for graph replay
    if (tid == 32)  g_npos[b] = 0;

    __threadfence();
    __syncthreads();
    if (tid == 0) {
        unsigned old = atomicAdd(&g_ticket, 1u);
        s_bc[2] = (old == BATCH - 1) ? 1 : 0;
    }
    __syncthreads();

    if (s_bc[2]) {
        float np = 0.f, lc = 0.f, pc = 0.f, ns = 0.f;
        if (tid < BATCH) {
            np = __ldcg(&g_nposf[tid]);
            lc = __ldcg(&g_locs[tid]);
            pc = __ldcg(&g_pces[tid]);
            ns = __ldcg(&g_negs[tid]);
        }
        np = brSumF(np, s_redf);
        lc = brSumF(lc, s_redf);
        pc = brSumF(pc, s_redf);
        ns = brSumF(ns, s_redf);
        if (tid == 0) {
            out[0] = (pc + ns) / (np + 1e-7f) + lc / (4.0f * np);
            g_ticket = 0u;
        }
    }
}

// ---------------- launch ------------------------------------------------------
extern "C" void kernel_launch(void* const* d_in, const int* in_sizes, int n_in,
                              void* d_out, int out_size) {
    const float* loc_preds  = (const float*)d_in[0];
    const float* conf_preds = (const float*)d_in[1];
    const float* boxes      = (const float*)d_in[2];
    const int*   labels     = (const int*)d_in[3];
    const float* priors     = (const float*)d_in[4];
    float* out = (float*)d_out;

    k1_iou<<<BATCH * NSLICE, 256>>>(boxes, priors);
    k2_ce<<<BATCH * CEB, 256>>>(conf_preds, labels);
    k3_select<<<BATCH, 1024>>>(loc_preds, boxes, priors, out);
    (void)in_sizes; (void)n_in; (void)out_size;
}

// round 6
// speedup vs baseline: 1.1274x; 1.1274x over previous
#include <cuda_runtime.h>
#include <cstdint>

#define BATCH 128
#define NPRI  8732
#define NOBJ  16
#define NCLS  21
#define THRESH 0.5f
#define CEB    35       // 256-prior blocks per image (35*256 >= 8732)
#define SL4    2183     // NPRI/4 exactly (k1b slice)

// ---------------- scratch (static device globals; zero-initialized) ----------
__device__ float              g_btov[BATCH * NPRI];
__device__ uint8_t            g_bti [BATCH * NPRI];
__device__ uint8_t            g_ct  [BATCH * NPRI];
__device__ uint8_t            g_of  [BATCH * NPRI];
__device__ float              g_ce  [BATCH * NPRI];
__device__ unsigned long long g_best[BATCH * NOBJ];  // re-zeroed by k3 each launch
__device__ int                g_npos[BATCH];         // re-zeroed by k3 each launch
__device__ float              g_nposf[BATCH];
__device__ float              g_locs[BATCH];
__device__ float              g_pces[BATCH];
__device__ float              g_negs[BATCH];
__device__ unsigned int       g_ticket;              // reset by last block each launch

// ---------------- helpers -----------------------------------------------------
__device__ __forceinline__ float sl1(float x) {
    float a = fabsf(x);
    return (a < 1.f) ? 0.5f * a * a : a - 0.5f;
}

__device__ __forceinline__ float brSumF(float v, float* s) {
    int lane = threadIdx.x & 31, wid = threadIdx.x >> 5;
    int nw = (blockDim.x + 31) >> 5;
    #pragma unroll
    for (int o = 16; o; o >>= 1) v += __shfl_xor_sync(0xFFFFFFFFu, v, o);
    if (lane == 0) s[wid] = v;
    __syncthreads();
    if (wid == 0) {
        float r = (lane < nw) ? s[lane] : 0.f;
        #pragma unroll
        for (int o = 16; o; o >>= 1) r += __shfl_xor_sync(0xFFFFFFFFu, r, o);
        if (lane == 0) s[0] = r;
    }
    __syncthreads();
    float r = s[0];
    __syncthreads();
    return r;
}

__device__ __forceinline__ int brSumI(int v, int* s) {
    int lane = threadIdx.x & 31, wid = threadIdx.x >> 5;
    int nw = (blockDim.x + 31) >> 5;
    #pragma unroll
    for (int o = 16; o; o >>= 1) v += __shfl_xor_sync(0xFFFFFFFFu, v, o);
    if (lane == 0) s[wid] = v;
    __syncthreads();
    if (wid == 0) {
        int r = (lane < nw) ? s[lane] : 0;
        #pragma unroll
        for (int o = 16; o; o >>= 1) r += __shfl_xor_sync(0xFFFFFFFFu, r, o);
        if (lane == 0) s[0] = r;
    }
    __syncthreads();
    int r = s[0];
    __syncthreads();
    return r;
}

// ---------------- K1a: per-prior argmax over truths (lean, no spills) --------
// grid = BATCH*CEB, one thread = one prior. Tracks only (pv,po); exact div.rn
// once per prior for the winning truth (threshold semantics exact).
__global__ __launch_bounds__(256)
void k1a_prior(const float* __restrict__ boxes, const float* __restrict__ priors) {
    const int b   = blockIdx.x / CEB;
    const int t   = blockIdx.x % CEB;
    const int tid = threadIdx.x;
    const int p   = t * 256 + tid;

    __shared__ float4 s_t[NOBJ];
    __shared__ float  s_ta[NOBJ];
    if (tid < NOBJ) {
        float4 tb = ((const float4*)boxes)[b * NOBJ + tid];
        s_t[tid]  = tb;
        s_ta[tid] = (tb.z - tb.x) * (tb.w - tb.y);
    }
    __syncthreads();

    if (p >= NPRI) return;
    float4 pr = ((const float4*)priors)[p];
    float hw = 0.5f * pr.z, hh = 0.5f * pr.w;
    float px1 = pr.x - hw, py1 = pr.y - hh, px2 = pr.x + hw, py2 = pr.y + hh;
    float ap = pr.z * pr.w;

    float pv = -1.f; int po = 0;
    #pragma unroll
    for (int o = 0; o < NOBJ; o++) {
        float4 tb = s_t[o];
        float ix = fmaxf(fminf(tb.z, px2) - fmaxf(tb.x, px1), 0.f);
        float iy = fmaxf(fminf(tb.w, py2) - fmaxf(tb.y, py1), 0.f);
        float inter = ix * iy;
        float den   = (s_ta[o] + ap) - inter;
        float v     = __fdividef(inter, den);   // ordering only
        bool g = v > pv;                        // first truth on tie
        pv = g ? v : pv;  po = g ? o : po;
    }
    // exact IoU for the winner only
    float4 tb = s_t[po];
    float ix = fmaxf(fminf(tb.z, px2) - fmaxf(tb.x, px1), 0.f);
    float iy = fmaxf(fminf(tb.w, py2) - fmaxf(tb.y, py1), 0.f);
    float inter = ix * iy;
    float den   = (s_ta[po] + ap) - inter;
    g_btov[b * NPRI + p] = inter / den;
    g_bti [b * NPRI + p] = (uint8_t)po;
}

// ---------------- K1b: per-truth best prior (warp-per-truth, reg-resident) ---
// 512 blocks = 4 slices per image, 512 threads = 16 warps, warp o = truth o.
// Priors staged to shared pre-converted (point form + area): per-pair cost ~15.
__global__ __launch_bounds__(512)
void k1b_truth(const float* __restrict__ boxes, const float* __restrict__ priors) {
    const int b    = blockIdx.x >> 2;
    const int s    = blockIdx.x & 3;
    const int tid  = threadIdx.x;
    const int lane = tid & 31;
    const int o    = tid >> 5;       // warp id == truth id
    const int lo   = s * SL4;

    __shared__ float4 s_p[SL4];      // point-form priors (x1,y1,x2,y2)
    __shared__ float  s_ap[SL4];     // prior areas
    __shared__ unsigned long long s_mrg[NOBJ];

    for (int i = tid; i < SL4; i += 512) {
        float4 pr = ((const float4*)priors)[lo + i];
        float hw = 0.5f * pr.z, hh = 0.5f * pr.w;
        s_p[i]  = make_float4(pr.x - hw, pr.y - hh, pr.x + hw, pr.y + hh);
        s_ap[i] = pr.z * pr.w;
    }
    // truth o in registers (broadcast load: all lanes same address)
    float4 tb = ((const float4*)boxes)[b * NOBJ + o];
    float sa  = (tb.z - tb.x) * (tb.w - tb.y);
    __syncthreads();

    float    bv = -1.f;
    unsigned bp = 0u;
    for (int i = lane; i < SL4; i += 32) {
        float4 q = s_p[i];
        float ix = fmaxf(fminf(tb.z, q.z) - fmaxf(tb.x, q.x), 0.f);
        float iy = fmaxf(fminf(tb.w, q.w) - fmaxf(tb.y, q.y), 0.f);
        float inter = ix * iy;
        float den   = (sa + s_ap[i]) - inter;
        float v     = __fdividef(inter, den);   // ordering only
        if (v > bv) { bv = v; bp = (unsigned)(lo + i); }  // first p on tie
    }

    unsigned long long key =
        ((unsigned long long)__float_as_uint(bv) << 32) |
        (unsigned)(0xFFFFFFFFu - bp);           // tie -> smaller p wins
    #pragma unroll
    for (int off = 16; off; off >>= 1) {
        unsigned long long u = __shfl_xor_sync(0xFFFFFFFFu, key, off);
        key = (u > key) ? u : key;
    }
    if (lane == 0) s_mrg[o] = key;              // avoid 16 separate atomics hot
    __syncthreads();
    if (tid < NOBJ)
        atomicMax(&g_best[b * NOBJ + tid], s_mrg[tid]);
}

// ---------------- K2: force-assign + conf target + cross entropy --------------
__global__ __launch_bounds__(256)
void k2_ce(const float* __restrict__ conf, const int* __restrict__ labels) {
    const int blk = blockIdx.x;
    const int b   = blk / CEB;
    const int t   = blk % CEB;
    const int tid = threadIdx.x;
    const int r0  = t * 256;
    const int nr  = min(256, NPRI - r0);

    __shared__ float    s_rows[256 * NCLS];
    __shared__ int      s_lab[NOBJ];
    __shared__ unsigned s_fp[NOBJ];
    __shared__ int      s_wc[8];

    if (tid < NOBJ) {
        s_lab[tid] = labels[b * NOBJ + tid];
        s_fp[tid]  = 0xFFFFFFFFu - (unsigned)(g_best[b * NOBJ + tid] & 0xFFFFFFFFULL);
    }
    const int nf4 = nr * NCLS / 4;
    const float4* src = (const float4*)(conf + ((size_t)b * NPRI + r0) * NCLS);
    #pragma unroll
    for (int i = 0; i < 6; i++) {
        int j = tid + i * 256;
        if (j < nf4) ((float4*)s_rows)[j] = src[j];
    }
    __syncthreads();

    int isp = 0;
    if (tid < nr) {
        int p = r0 + tid;
        size_t idx = (size_t)b * NPRI + p;
        float ov = g_btov[idx];
        int   o  = g_bti[idx];
        #pragma unroll
        for (int oo = 0; oo < NOBJ; oo++) {          // ascending: last truth wins
            bool f = (s_fp[oo] == (unsigned)p);
            ov = f ? 2.0f : ov;
            o  = f ? oo : o;
        }
        int ct = (ov < THRESH) ? 0 : (s_lab[o] + 1);
        g_ct[idx] = (uint8_t)ct;
        g_of[idx] = (uint8_t)o;
        isp = (ct > 0);
        const float* v = s_rows + tid * NCLS;        // stride 21: conflict-free
        float m = v[0];
        #pragma unroll
        for (int c = 1; c < NCLS; c++) m = fmaxf(m, v[c]);
        float ssum = 0.f;
        #pragma unroll
        for (int c = 0; c < NCLS; c++) ssum += __expf(v[c] - m);
        g_ce[idx] = m + __logf(ssum) - v[ct];
    }
    unsigned bal = __ballot_sync(0xFFFFFFFFu, isp);
    if ((tid & 31) == 0) s_wc[tid >> 5] = __popc(bal);
    __syncthreads();
    if (tid == 0) {
        int c = 0;
        #pragma unroll
        for (int w = 0; w < 8; w++) c += s_wc[w];
        atomicAdd(&g_npos[b], c);
    }
}

// ---------------- K3: loc loss + register-resident top-K + fused final --------
__global__ __launch_bounds__(1024)
void k3_select(const float* __restrict__ loc_preds,
               const float* __restrict__ boxes,
               const float* __restrict__ priors,
               float* __restrict__ out) {
    const int b   = blockIdx.x;
    const int tid = threadIdx.x;

    __shared__ float s_tx1[NOBJ], s_ty1[NOBJ], s_tx2[NOBJ], s_ty2[NOBJ];
    __shared__ float s_redf[32];
    __shared__ int   s_redi[32];
    __shared__ int   s_wc[32];
    __shared__ int   s_bc[4];

    if (tid < NOBJ) {
        s_tx1[tid] = boxes[(b * NOBJ + tid) * 4 + 0];
        s_ty1[tid] = boxes[(b * NOBJ + tid) * 4 + 1];
        s_tx2[tid] = boxes[(b * NOBJ + tid) * 4 + 2];
        s_ty2[tid] = boxes[(b * NOBJ + tid) * 4 + 3];
    }
    if (tid == 0) s_bc[0] = g_npos[b];
    __syncthreads();
    const int npos = s_bc[0];

    unsigned u[9];
    float posce = 0.f, locsum = 0.f;
    #pragma unroll
    for (int i = 0; i < 9; i++) {
        int p = tid + i * 1024;
        u[i] = 0u;
        if (p < NPRI) {
            size_t idx = (size_t)b * NPRI + p;
            float ce = g_ce[idx];
            if (g_ct[idx] > 0) {
                posce += ce;
                int o = g_of[idx];
                float4 pr = ((const float4*)priors)[p];
                float tx1 = s_tx1[o], ty1 = s_ty1[o], tx2 = s_tx2[o], ty2 = s_ty2[o];
                float g0 = ((tx1 + tx2) * 0.5f - pr.x) / (0.1f * pr.z);
                float g1 = ((ty1 + ty2) * 0.5f - pr.y) / (0.1f * pr.w);
                float g2 = __logf((tx2 - tx1) / pr.z) * 5.0f;
                float g3 = __logf((ty2 - ty1) / pr.w) * 5.0f;
                float4 lp = ((const float4*)loc_preds)[(size_t)b * NPRI + p];
                locsum += sl1(lp.x - g0) + sl1(lp.y - g1)
                        + sl1(lp.z - g2) + sl1(lp.w - g3);
            } else {
                u[i] = __float_as_uint(ce);   // negatives only; ce >= 0
            }
        }
    }

    float pcT = brSumF(posce, s_redf);
    float lcT = brSumF(locsum, s_redf);

    int K = 3 * npos; if (K > NPRI) K = NPRI;
    float negsum = 0.f;
    if (K > 0) {
        unsigned prefix = 0u;
        for (int bit = 30; bit >= 0; bit--) {
            unsigned cand = prefix | (1u << bit);
            int c = 0;
            #pragma unroll
            for (int i = 0; i < 9; i++)
                c += __popc(__ballot_sync(0xFFFFFFFFu, u[i] >= cand));
            if ((tid & 31) == 0) s_wc[tid >> 5] = c;
            __syncthreads();
            if (tid < 32) {
                int t2 = s_wc[tid];
                #pragma unroll
                for (int off = 16; off; off >>= 1)
                    t2 += __shfl_xor_sync(0xFFFFFFFFu, t2, off);
                if (tid == 0) s_bc[1] = t2;
            }
            __syncthreads();
            if (s_bc[1] >= K) prefix = cand;
        }
        float vK = __uint_as_float(prefix);
        float sgt = 0.f; int cgt = 0;
        #pragma unroll
        for (int i = 0; i < 9; i++) {
            float v = __uint_as_float(u[i]);
            if (v > vK) { sgt += v; cgt++; }
        }
        sgt = brSumF(sgt, s_redf);
        cgt = brSumI(cgt, s_redi);
        negsum = sgt + (float)(K - cgt) * vK;
    }

    if (tid == 0) {
        g_locs[b]  = lcT;
        g_pces[b]  = pcT;
        g_negs[b]  = negsum;
        g_nposf[b] = (float)npos;
    }
    if (tid < NOBJ) g_best[b * NOBJ + tid] = 0ULL;   // re-zero for graph replay
    if (tid == 32)  g_npos[b] = 0;

    __threadfence();
    __syncthreads();
    if (tid == 0) {
        unsigned old = atomicAdd(&g_ticket, 1u);
        s_bc[2] = (old == BATCH - 1) ? 1 : 0;
    }
    __syncthreads();

    if (s_bc[2]) {
        float np = 0.f, lc = 0.f, pc = 0.f, ns = 0.f;
        if (tid < BATCH) {
            np = __ldcg(&g_nposf[tid]);
            lc = __ldcg(&g_locs[tid]);
            pc = __ldcg(&g_pces[tid]);
            ns = __ldcg(&g_negs[tid]);
        }
        np = brSumF(np, s_redf);
        lc = brSumF(lc, s_redf);
        pc = brSumF(pc, s_redf);
        ns = brSumF(ns, s_redf);
        if (tid == 0) {
            out[0] = (pc + ns) / (np + 1e-7f) + lc / (4.0f * np);
            g_ticket = 0u;
        }
    }
}

// ---------------- launch ------------------------------------------------------
extern "C" void kernel_launch(void* const* d_in, const int* in_sizes, int n_in,
                              void* d_out, int out_size) {
    const float* loc_preds  = (const float*)d_in[0];
    const float* conf_preds = (const float*)d_in[1];
    const float* boxes      = (const float*)d_in[2];
    const int*   labels     = (const int*)d_in[3];
    const float* priors     = (const float*)d_in[4];
    float* out = (float*)d_out;

    k1a_prior<<<BATCH * CEB, 256>>>(boxes, priors);
    k1b_truth<<<BATCH * 4, 512>>>(boxes, priors);
    k2_ce<<<BATCH * CEB, 256>>>(conf_preds, labels);
    k3_select<<<BATCH, 1024>>>(loc_preds, boxes, priors, out);
    (void)in_sizes; (void)n_in; (void)out_size;
}

// round 8
// speedup vs baseline: 1.2649x; 1.1220x over previous
#include <cuda_runtime.h>
#include <cstdint>

#define BATCH 128
#define NPRI  8732
#define NOBJ  16
#define NCLS  21
#define THRESH 0.5f
#define CEB    35       // 256-prior blocks per image (35*256 >= 8732)

// ---------------- scratch (static device globals; zero-initialized) ----------
__device__ float              g_btov[BATCH * NPRI];
__device__ uint8_t            g_bti [BATCH * NPRI];
__device__ uint8_t            g_ct  [BATCH * NPRI];
__device__ uint8_t            g_of  [BATCH * NPRI];
__device__ float              g_ce  [BATCH * NPRI];
__device__ unsigned long long g_best[BATCH * NOBJ];  // re-zeroed by k3 each launch
__device__ int                g_npos[BATCH];         // re-zeroed by k3 each launch
__device__ float              g_nposf[BATCH];
__device__ float              g_locs[BATCH];
__device__ float              g_pces[BATCH];
__device__ float              g_negs[BATCH];
__device__ unsigned int       g_ticket;              // reset by last block each launch

// ---------------- helpers -----------------------------------------------------
__device__ __forceinline__ float sl1(float x) {
    float a = fabsf(x);
    return (a < 1.f) ? 0.5f * a * a : a - 0.5f;
}

__device__ __forceinline__ float brSumF(float v, float* s) {
    int lane = threadIdx.x & 31, wid = threadIdx.x >> 5;
    int nw = (blockDim.x + 31) >> 5;
    #pragma unroll
    for (int o = 16; o; o >>= 1) v += __shfl_xor_sync(0xFFFFFFFFu, v, o);
    if (lane == 0) s[wid] = v;
    __syncthreads();
    if (wid == 0) {
        float r = (lane < nw) ? s[lane] : 0.f;
        #pragma unroll
        for (int o = 16; o; o >>= 1) r += __shfl_xor_sync(0xFFFFFFFFu, r, o);
        if (lane == 0) s[0] = r;
    }
    __syncthreads();
    float r = s[0];
    __syncthreads();
    return r;
}

__device__ __forceinline__ int brSumI(int v, int* s) {
    int lane = threadIdx.x & 31, wid = threadIdx.x >> 5;
    int nw = (blockDim.x + 31) >> 5;
    v = __reduce_add_sync(0xFFFFFFFFu, v);
    if (lane == 0) s[wid] = v;
    __syncthreads();
    if (wid == 0) {
        int r = (lane < nw) ? s[lane] : 0;
        r = __reduce_add_sync(0xFFFFFFFFu, r);
        if (lane == 0) s[0] = r;
    }
    __syncthreads();
    int r = s[0];
    __syncthreads();
    return r;
}

// ---------------- K1: fused matching (per-prior AND per-truth argmax) ---------
// grid = BATCH*CEB, one thread = one prior. Per-truth best reduced inline via
// REDUX.UMAX on IoU bits (IoU >= 0 so uint order == float order).
__global__ __launch_bounds__(256)
void k1_match(const float* __restrict__ boxes, const float* __restrict__ priors) {
    const int b    = blockIdx.x / CEB;
    const int t    = blockIdx.x % CEB;
    const int tid  = threadIdx.x;
    const int p    = t * 256 + tid;
    const int lane = tid & 31, wid = tid >> 5;
    const bool valid = (p < NPRI);

    __shared__ float4 s_t[NOBJ];
    __shared__ float  s_ta[NOBJ];
    __shared__ unsigned long long s_red[NOBJ][8];

    if (tid < NOBJ) {
        float4 tb = ((const float4*)boxes)[b * NOBJ + tid];
        s_t[tid]  = tb;
        s_ta[tid] = (tb.z - tb.x) * (tb.w - tb.y);
    }
    __syncthreads();

    // invalid tail threads use a far-away degenerate box -> IoU exactly 0,
    // and their p >= NPRI loses every tie-break. Keeps warp collectives full.
    float px1 = 2.f, py1 = 2.f, px2 = 2.f, py2 = 2.f, ap = 0.f;
    if (valid) {
        float4 pr = ((const float4*)priors)[p];
        float hw = 0.5f * pr.z, hh = 0.5f * pr.w;
        px1 = pr.x - hw; py1 = pr.y - hh; px2 = pr.x + hw; py2 = pr.y + hh;
        ap = pr.z * pr.w;
    }

    float pv = -1.f; int po = 0;
    #pragma unroll
    for (int o = 0; o < NOBJ; o++) {
        float4 tb = s_t[o];
        float ix = fmaxf(fminf(tb.z, px2) - fmaxf(tb.x, px1), 0.f);
        float iy = fmaxf(fminf(tb.w, py2) - fmaxf(tb.y, py1), 0.f);
        float inter = ix * iy;
        float den   = (s_ta[o] + ap) - inter;
        float v     = __fdividef(inter, den);   // ordering only
        bool g = v > pv;                        // first truth on tie
        pv = g ? v : pv;  po = g ? o : po;
        // per-truth warp max: REDUX on bits, lowest winning lane = smallest p
        unsigned vb = __float_as_uint(v);
        unsigned vm = __reduce_max_sync(0xFFFFFFFFu, vb);
        unsigned msk = __ballot_sync(0xFFFFFFFFu, vb == vm);
        if (lane == __ffs(msk) - 1)
            s_red[o][wid] = ((unsigned long long)vm << 32)
                          | (unsigned)(0xFFFFFFFFu - (unsigned)p);
    }

    if (valid) {
        // exact IoU for the winning truth only (threshold semantics exact)
        float4 tb = s_t[po];
        float ix = fmaxf(fminf(tb.z, px2) - fmaxf(tb.x, px1), 0.f);
        float iy = fmaxf(fminf(tb.w, py2) - fmaxf(tb.y, py1), 0.f);
        float inter = ix * iy;
        float den   = (s_ta[po] + ap) - inter;
        g_btov[b * NPRI + p] = inter / den;     // div.rn, once per prior
        g_bti [b * NPRI + p] = (uint8_t)po;
    }

    __syncthreads();
    if (tid < NOBJ) {
        unsigned long long m = 0ULL;
        #pragma unroll
        for (int w = 0; w < 8; w++) {
            unsigned long long u = s_red[tid][w];
            m = (u > m) ? u : m;
        }
        atomicMax(&g_best[b * NOBJ + tid], m);  // order-independent merge
    }
}

// ---------------- K2: force-assign + conf target + cross entropy --------------
__global__ __launch_bounds__(256)
void k2_ce(const float* __restrict__ conf, const int* __restrict__ labels) {
    const int blk = blockIdx.x;
    const int b   = blk / CEB;
    const int t   = blk % CEB;
    const int tid = threadIdx.x;
    const int r0  = t * 256;
    const int nr  = min(256, NPRI - r0);

    __shared__ float    s_rows[256 * NCLS];
    __shared__ int      s_lab[NOBJ];
    __shared__ unsigned s_fp[NOBJ];
    __shared__ int      s_wc[8];

    if (tid < NOBJ) {
        s_lab[tid] = labels[b * NOBJ + tid];
        s_fp[tid]  = 0xFFFFFFFFu - (unsigned)(g_best[b * NOBJ + tid] & 0xFFFFFFFFULL);
    }
    const int nf4 = nr * NCLS / 4;
    const float4* src = (const float4*)(conf + ((size_t)b * NPRI + r0) * NCLS);
    #pragma unroll
    for (int i = 0; i < 6; i++) {
        int j = tid + i * 256;
        if (j < nf4) ((float4*)s_rows)[j] = src[j];
    }
    __syncthreads();

    int isp = 0;
    if (tid < nr) {
        int p = r0 + tid;
        size_t idx = (size_t)b * NPRI + p;
        float ov = g_btov[idx];
        int   o  = g_bti[idx];
        #pragma unroll
        for (int oo = 0; oo < NOBJ; oo++) {          // ascending: last truth wins
            bool f = (s_fp[oo] == (unsigned)p);
            ov = f ? 2.0f : ov;
            o  = f ? oo : o;
        }
        int ct = (ov < THRESH) ? 0 : (s_lab[o] + 1);
        g_ct[idx] = (uint8_t)ct;
        g_of[idx] = (uint8_t)o;
        isp = (ct > 0);
        const float* v = s_rows + tid * NCLS;        // stride 21: conflict-free
        float m = v[0];
        #pragma unroll
        for (int c = 1; c < NCLS; c++) m = fmaxf(m, v[c]);
        float ssum = 0.f;
        #pragma unroll
        for (int c = 0; c < NCLS; c++) ssum += __expf(v[c] - m);
        g_ce[idx] = m + __logf(ssum) - v[ct];
    }
    int c = __reduce_add_sync(0xFFFFFFFFu, isp);
    if ((tid & 31) == 0) s_wc[tid >> 5] = c;
    __syncthreads();
    if (tid == 0) {
        int cc = 0;
        #pragma unroll
        for (int w = 0; w < 8; w++) cc += s_wc[w];
        atomicAdd(&g_npos[b], cc);
    }
}

// ---------------- K3: loc loss + 2-bit radix top-K + fused final --------------
__global__ __launch_bounds__(1024)
void k3_select(const float* __restrict__ loc_preds,
               const float* __restrict__ boxes,
               const float* __restrict__ priors,
               float* __restrict__ out) {
    const int b    = blockIdx.x;
    const int tid  = threadIdx.x;
    const int lane = tid & 31, wid = tid >> 5;

    __shared__ float s_tx1[NOBJ], s_ty1[NOBJ], s_tx2[NOBJ], s_ty2[NOBJ];
    __shared__ float s_redf[32];
    __shared__ int   s_redi[32];
    __shared__ int   s_c1[32], s_c2[32], s_c3[32];
    __shared__ int   s_tot[4];
    __shared__ int   s_bc[4];

    if (tid < NOBJ) {
        s_tx1[tid] = boxes[(b * NOBJ + tid) * 4 + 0];
        s_ty1[tid] = boxes[(b * NOBJ + tid) * 4 + 1];
        s_tx2[tid] = boxes[(b * NOBJ + tid) * 4 + 2];
        s_ty2[tid] = boxes[(b * NOBJ + tid) * 4 + 3];
    }
    if (tid == 0) s_bc[0] = g_npos[b];
    __syncthreads();
    const int npos = s_bc[0];

    unsigned u[9];
    float posce = 0.f, locsum = 0.f;
    #pragma unroll
    for (int i = 0; i < 9; i++) {
        int p = tid + i * 1024;
        u[i] = 0u;
        if (p < NPRI) {
            size_t idx = (size_t)b * NPRI + p;
            float ce = g_ce[idx];
            if (g_ct[idx] > 0) {
                posce += ce;
                int o = g_of[idx];
                float4 pr = ((const float4*)priors)[p];
                float tx1 = s_tx1[o], ty1 = s_ty1[o], tx2 = s_tx2[o], ty2 = s_ty2[o];
                float g0 = ((tx1 + tx2) * 0.5f - pr.x) / (0.1f * pr.z);
                float g1 = ((ty1 + ty2) * 0.5f - pr.y) / (0.1f * pr.w);
                float g2 = __logf((tx2 - tx1) / pr.z) * 5.0f;
                float g3 = __logf((ty2 - ty1) / pr.w) * 5.0f;
                float4 lp = ((const float4*)loc_preds)[(size_t)b * NPRI + p];
                locsum += sl1(lp.x - g0) + sl1(lp.y - g1)
                        + sl1(lp.z - g2) + sl1(lp.w - g3);
            } else {
                u[i] = __float_as_uint(ce);   // negatives only; ce >= 0
            }
        }
    }

    float pcT = brSumF(posce, s_redf);
    float lcT = brSumF(locsum, s_redf);

    int K = 3 * npos; if (K > NPRI) K = NPRI;
    float negsum = 0.f;
    if (K > 0) {
        unsigned prefix = 0u;
        // 15 rounds x 2 bits (bits 30..1), then 1 round for bit 0
        for (int sh = 29; sh >= 1; sh -= 2) {
            unsigned cA = prefix | (1u << sh);
            unsigned cB = prefix | (2u << sh);
            unsigned cC = prefix | (3u << sh);
            int n1 = 0, n2 = 0, n3 = 0;
            #pragma unroll
            for (int i = 0; i < 9; i++) {
                n1 += (u[i] >= cA);
                n2 += (u[i] >= cB);
                n3 += (u[i] >= cC);
            }
            n1 = __reduce_add_sync(0xFFFFFFFFu, n1);
            n2 = __reduce_add_sync(0xFFFFFFFFu, n2);
            n3 = __reduce_add_sync(0xFFFFFFFFu, n3);
            if (lane == 0) { s_c1[wid] = n1; s_c2[wid] = n2; s_c3[wid] = n3; }
            __syncthreads();
            if (tid < 96) {          // 3 warps reduce the 3 counts in parallel
                int w = tid >> 5, l = tid & 31;
                int v = (w == 0) ? s_c1[l] : (w == 1) ? s_c2[l] : s_c3[l];
                v = __reduce_add_sync(0xFFFFFFFFu, v);
                if (l == 0) s_tot[w] = v;
            }
            __syncthreads();
            int t1 = s_tot[0], t2 = s_tot[1], t3 = s_tot[2];
            prefix |= (t3 >= K) ? (3u << sh)
                    : (t2 >= K) ? (2u << sh)
                    : (t1 >= K) ? (1u << sh) : 0u;
            __syncthreads();
        }
        {   // final bit 0
            unsigned cand = prefix | 1u;
            int n = 0;
            #pragma unroll
            for (int i = 0; i < 9; i++) n += (u[i] >= cand);
            n = __reduce_add_sync(0xFFFFFFFFu, n);
            if (lane == 0) s_c1[wid] = n;
            __syncthreads();
            if (tid < 32) {
                int v = __reduce_add_sync(0xFFFFFFFFu, s_c1[tid]);
                if (tid == 0) s_tot[0] = v;
            }
            __syncthreads();
            if (s_tot[0] >= K) prefix |= 1u;
        }
        float vK = __uint_as_float(prefix);       // exact K-th largest
        float sgt = 0.f; int cgt = 0;
        #pragma unroll
        for (int i = 0; i < 9; i++) {
            float v = __uint_as_float(u[i]);
            if (v > vK) { sgt += v; cgt++; }
        }
        sgt = brSumF(sgt, s_redf);
        cgt = brSumI(cgt, s_redi);
        negsum = sgt + (float)(K - cgt) * vK;     // ties handled exactly
    }

    if (tid == 0) {
        g_locs[b]  = lcT;
        g_pces[b]  = pcT;
        g_negs[b]  = negsum;
        g_nposf[b] = (float)npos;
    }
    if (tid < NOBJ) g_best[b * NOBJ + tid] = 0ULL;   // re-zero for graph replay
    if (tid == 32)  g_npos[b] = 0;

    __threadfence();
    __syncthreads();
    if (tid == 0) {
        unsigned old = atomicAdd(&g_ticket, 1u);
        s_bc[2] = (old == BATCH - 1) ? 1 : 0;
    }
    __syncthreads();

    if (s_bc[2]) {
        float np = 0.f, lc = 0.f, pc = 0.f, ns = 0.f;
        if (tid < BATCH) {
            np = __ldcg(&g_nposf[tid]);
            lc = __ldcg(&g_locs[tid]);
            pc = __ldcg(&g_pces[tid]);
            ns = __ldcg(&g_negs[tid]);
        }
        np = brSumF(np, s_redf);
        lc = brSumF(lc, s_redf);
        pc = brSumF(pc, s_redf);
        ns = brSumF(ns, s_redf);
        if (tid == 0) {
            out[0] = (pc + ns) / (np + 1e-7f) + lc / (4.0f * np);
            g_ticket = 0u;
        }
    }
}

// ---------------- launch ------------------------------------------------------
extern "C" void kernel_launch(void* const* d_in, const int* in_sizes, int n_in,
                              void* d_out, int out_size) {
    const float* loc_preds  = (const float*)d_in[0];
    const float* conf_preds = (const float*)d_in[1];
    const float* boxes      = (const float*)d_in[2];
    const int*   labels     = (const int*)d_in[3];
    const float* priors     = (const float*)d_in[4];
    float* out = (float*)d_out;

    k1_match<<<BATCH * CEB, 256>>>(boxes, priors);
    k2_ce<<<BATCH * CEB, 256>>>(conf_preds, labels);
    k3_select<<<BATCH, 1024>>>(loc_preds, boxes, priors, out);
    (void)in_sizes; (void)n_in; (void)out_size;
}